// round 2
// baseline (speedup 1.0000x reference)
#include <cuda_runtime.h>
#include <math.h>

#define N_NODES 20000
#define DIM 128
#define KNB 16
#define STEPS 2
#define LAYERS 2
#define E_EDGES 8192
#define EDGE_BLOCKS (E_EDGES / 8)   // 8 warps (edges) per 256-thread block = 1024

// Scratch (static __device__ — no allocations allowed)
__device__ float g_proj[N_NODES];
__device__ float g_self[N_NODES];
__device__ float g_att[N_NODES * DIM];
__device__ float g_cw[LAYERS * DIM];
__device__ float g_partials[EDGE_BLOCKS];

// ---------------------------------------------------------------------------
// K0: cw[l,d] = sum_f layer_w[l,f,d]   (the einsum contracts f, not d!)
// ---------------------------------------------------------------------------
__global__ void cw_kernel(const float* __restrict__ layer_w) {
    int t = blockIdx.x * blockDim.x + threadIdx.x;  // 0..255
    if (t < LAYERS * DIM) {
        int l = t >> 7, d = t & 127;
        const float* w = layer_w + l * DIM * DIM + d;
        float s = 0.f;
#pragma unroll 16
        for (int f = 0; f < DIM; f++) s += w[f * DIM];
        g_cw[t] = s;
    }
}

// ---------------------------------------------------------------------------
// K1: proj[n] = emb[n]·w_n,  self[n] = emb[n]·w_s   (one warp per node)
// ---------------------------------------------------------------------------
__global__ void proj_kernel(const float* __restrict__ emb,
                            const float* __restrict__ fc_w) {
    int warp = (blockIdx.x * blockDim.x + threadIdx.x) >> 5;
    int lane = threadIdx.x & 31;
    if (warp >= N_NODES) return;
    float4 e  = reinterpret_cast<const float4*>(emb + (size_t)warp * DIM)[lane];
    float4 wn = reinterpret_cast<const float4*>(fc_w)[lane];
    float4 ws = reinterpret_cast<const float4*>(fc_w + DIM)[lane];
    float pn = e.x * wn.x + e.y * wn.y + e.z * wn.z + e.w * wn.w;
    float ps = e.x * ws.x + e.y * ws.y + e.z * ws.z + e.w * ws.w;
#pragma unroll
    for (int off = 16; off; off >>= 1) {
        pn += __shfl_xor_sync(0xffffffffu, pn, off);
        ps += __shfl_xor_sync(0xffffffffu, ps, off);
    }
    if (lane == 0) { g_proj[warp] = pn; g_self[warp] = ps; }
}

// ---------------------------------------------------------------------------
// K2: attention aggregation. One warp per node.
//   att[n] = sum_s ( sum_k softmax(leaky(proj[nb]+self[n]+b))_k * emb[nb_k] )
//            + STEPS*K * emb[n]
// ---------------------------------------------------------------------------
__global__ void att_kernel(const float* __restrict__ emb,
                           const int*   __restrict__ neighbors,
                           const float* __restrict__ fc_b) {
    int warp = (blockIdx.x * blockDim.x + threadIdx.x) >> 5;
    int lane = threadIdx.x & 31;
    if (warp >= N_NODES) return;
    const int node = warp;
    const float fcb   = fc_b[0];
    const float selfv = g_self[node];

    // acc starts at (STEPS*K) * own embedding = 32 * emb[node]
    float4 me = reinterpret_cast<const float4*>(emb + (size_t)node * DIM)[lane];
    float4 acc;
    acc.x = 32.f * me.x; acc.y = 32.f * me.y;
    acc.z = 32.f * me.z; acc.w = 32.f * me.w;

#pragma unroll
    for (int s = 0; s < STEPS; s++) {
        int nb = 0;
        float sc = -1e30f;
        if (lane < KNB) {
            nb = neighbors[(size_t)s * N_NODES * KNB + (size_t)node * KNB + lane];
            sc = g_proj[nb] + selfv + fcb;
            sc = (sc >= 0.f) ? sc : 0.2f * sc;   // leaky relu 0.2
        }
        // 16-lane max (offsets <=8 stay within each 16-lane half)
        float m = sc;
#pragma unroll
        for (int off = 8; off; off >>= 1)
            m = fmaxf(m, __shfl_xor_sync(0xffffffffu, m, off));
        float ex = (lane < KNB) ? __expf(sc - m) : 0.f;
        float ssum = ex;
#pragma unroll
        for (int off = 8; off; off >>= 1)
            ssum += __shfl_xor_sync(0xffffffffu, ssum, off);
        float wgt = ex / ssum;   // valid on lanes 0..15

        // weighted gather-accumulate: 16 neighbors, float4 per lane (coalesced)
#pragma unroll
        for (int k = 0; k < KNB; k++) {
            float wk = __shfl_sync(0xffffffffu, wgt, k);
            int   ik = __shfl_sync(0xffffffffu, nb,  k);
            float4 v = reinterpret_cast<const float4*>(emb + (size_t)ik * DIM)[lane];
            acc.x += wk * v.x; acc.y += wk * v.y;
            acc.z += wk * v.z; acc.w += wk * v.w;
        }
    }
    reinterpret_cast<float4*>(g_att + (size_t)node * DIM)[lane] = acc;
}

// ---------------------------------------------------------------------------
// K3: per-edge loss partials. One warp per edge, 8 edges per block.
//   src_sum[d] = sum_l relu(x[d]*cw[l,d] + lb[l,d]); diff = ||ssum-dsum||²/D
//   loss = 0.5*(label - exp(-diff))²  -> per-block partial (deterministic)
// ---------------------------------------------------------------------------
__global__ void edge_kernel(const float* __restrict__ emb,
                            const int*   __restrict__ edges,
                            const int*   __restrict__ labels,
                            const float* __restrict__ layer_b) {
    __shared__ float wsum[8];
    int warp_in_blk = threadIdx.x >> 5;
    int lane = threadIdx.x & 31;
    int e = blockIdx.x * 8 + warp_in_blk;

    float loss = 0.f;
    {
        int src = edges[2 * e];
        int dst = edges[2 * e + 1];
        int lab = labels[e];
        const float* base = (lab == 1) ? g_att : emb;
        float4 se = reinterpret_cast<const float4*>(base + (size_t)src * DIM)[lane];
        float4 de = reinterpret_cast<const float4*>(base + (size_t)dst * DIM)[lane];

        float acc = 0.f;
        float ss, ds, dd;
#pragma unroll
        for (int l = 0; l < LAYERS; l++) {
            float4 c = reinterpret_cast<const float4*>(g_cw + l * DIM)[lane];
            float4 b = reinterpret_cast<const float4*>(layer_b + l * DIM)[lane];
            // component x
            ss = fmaxf(se.x * c.x + b.x, 0.f); ds = fmaxf(de.x * c.x + b.x, 0.f);
            if (l == 0) { /* init */ }
            // accumulate per-component layer sums in registers
            // unrolled manually below
            (void)ss; (void)ds;
        }
        // redo cleanly: per-component layer sums
        float sx = 0, sy = 0, sz = 0, sw = 0;
        float dx = 0, dy = 0, dz = 0, dw = 0;
#pragma unroll
        for (int l = 0; l < LAYERS; l++) {
            float4 c = reinterpret_cast<const float4*>(g_cw + l * DIM)[lane];
            float4 b = reinterpret_cast<const float4*>(layer_b + l * DIM)[lane];
            sx += fmaxf(se.x * c.x + b.x, 0.f);
            sy += fmaxf(se.y * c.y + b.y, 0.f);
            sz += fmaxf(se.z * c.z + b.z, 0.f);
            sw += fmaxf(se.w * c.w + b.w, 0.f);
            dx += fmaxf(de.x * c.x + b.x, 0.f);
            dy += fmaxf(de.y * c.y + b.y, 0.f);
            dz += fmaxf(de.z * c.z + b.z, 0.f);
            dw += fmaxf(de.w * c.w + b.w, 0.f);
        }
        dd = sx - dx; acc += dd * dd;
        dd = sy - dy; acc += dd * dd;
        dd = sz - dz; acc += dd * dd;
        dd = sw - dw; acc += dd * dd;
#pragma unroll
        for (int off = 16; off; off >>= 1)
            acc += __shfl_xor_sync(0xffffffffu, acc, off);
        if (lane == 0) {
            float diff = acc * (1.f / (float)DIM);
            float p = expf(-diff);
            float lf = (float)lab;
            loss = 0.5f * (lf - p) * (lf - p);
        }
    }
    if (lane == 0) wsum[warp_in_blk] = loss;
    __syncthreads();
    if (threadIdx.x == 0) {
        float s = 0.f;
#pragma unroll
        for (int i = 0; i < 8; i++) s += wsum[i];
        g_partials[blockIdx.x] = s;
    }
}

// ---------------------------------------------------------------------------
// K4: deterministic final reduction of EDGE_BLOCKS partials -> d_out[0]
// ---------------------------------------------------------------------------
__global__ void reduce_kernel(float* __restrict__ out) {
    __shared__ float sh[1024];
    int t = threadIdx.x;
    sh[t] = g_partials[t];
    __syncthreads();
#pragma unroll
    for (int stride = 512; stride; stride >>= 1) {
        if (t < stride) sh[t] += sh[t + stride];
        __syncthreads();
    }
    if (t == 0) out[0] = sh[0];
}

// ---------------------------------------------------------------------------
// Inputs (metadata order): 0 edges(i32 E*2), 1 labels(i32 E), 2 neighbors(i32
// STEPS*N*K), 3 embeddings(f32 N*D), 4 fc_w(f32 2D), 5 fc_b(f32 1),
// 6 layer_w(f32 L*D*D), 7 layer_b(f32 L*D). Output: f32 scalar.
// ---------------------------------------------------------------------------
extern "C" void kernel_launch(void* const* d_in, const int* in_sizes, int n_in,
                              void* d_out, int out_size) {
    const int*   edges     = (const int*)  d_in[0];
    const int*   labels    = (const int*)  d_in[1];
    const int*   neighbors = (const int*)  d_in[2];
    const float* emb       = (const float*)d_in[3];
    const float* fc_w      = (const float*)d_in[4];
    const float* fc_b      = (const float*)d_in[5];
    const float* layer_w   = (const float*)d_in[6];
    const float* layer_b   = (const float*)d_in[7];
    float* out = (float*)d_out;

    const int warps_per_blk = 8;                       // 256 threads
    int node_blocks = (N_NODES + warps_per_blk - 1) / warps_per_blk;  // 2500

    cw_kernel<<<1, 256>>>(layer_w);
    proj_kernel<<<node_blocks, 256>>>(emb, fc_w);
    att_kernel<<<node_blocks, 256>>>(emb, neighbors, fc_b);
    edge_kernel<<<EDGE_BLOCKS, 256>>>(emb, edges, labels, layer_b);
    reduce_kernel<<<1, 1024>>>(out);
}

// round 4
// speedup vs baseline: 1.0683x; 1.0683x over previous
#include <cuda_runtime.h>
#include <math.h>

#define N_NODES 20000
#define DIM 128
#define KNB 16
#define STEPS 2
#define LAYERS 2
#define E_EDGES 8192
#define EDGES_PER_WARP 2
#define EDGE_WARPS_PER_BLK 8
#define EDGE_BLOCKS (E_EDGES / (EDGES_PER_WARP * EDGE_WARPS_PER_BLK))  // 512

// Scratch (static __device__ — no allocations allowed)
__device__ float g_proj[N_NODES];
__device__ float g_self[N_NODES];
__device__ float g_att[N_NODES * DIM];
__device__ float g_cw[LAYERS * DIM];
__device__ float g_partials[EDGE_BLOCKS];
__device__ int   g_edge_count;

// ---------------------------------------------------------------------------
// K1: fused — proj[n] = emb[n]·w_n, self[n] = emb[n]·w_s  (one warp/node)
//     block 0 additionally computes cw[l,d] = sum_f layer_w[l,f,d]
//     and resets the edge completion counter for this graph replay.
// ---------------------------------------------------------------------------
__global__ void __launch_bounds__(256) proj_cw_kernel(
        const float* __restrict__ emb,
        const float* __restrict__ fc_w,
        const float* __restrict__ layer_w) {
    // --- cw + counter reset on block 0 (tiny extra work) ---
    if (blockIdx.x == 0) {
        int t = threadIdx.x;                      // 0..255 == LAYERS*DIM
        int l = t >> 7, d = t & 127;
        const float* w = layer_w + l * DIM * DIM + d;
        float s = 0.f;
#pragma unroll 16
        for (int f = 0; f < DIM; f++) s += w[f * DIM];
        g_cw[t] = s;
        if (t == 0) g_edge_count = 0;
    }

    int warp = (blockIdx.x * blockDim.x + threadIdx.x) >> 5;
    int lane = threadIdx.x & 31;
    if (warp >= N_NODES) return;
    float4 e  = reinterpret_cast<const float4*>(emb + (size_t)warp * DIM)[lane];
    float4 wn = reinterpret_cast<const float4*>(fc_w)[lane];
    float4 ws = reinterpret_cast<const float4*>(fc_w + DIM)[lane];
    float pn = e.x * wn.x + e.y * wn.y + e.z * wn.z + e.w * wn.w;
    float ps = e.x * ws.x + e.y * ws.y + e.z * ws.z + e.w * ws.w;
#pragma unroll
    for (int off = 16; off; off >>= 1) {
        pn += __shfl_xor_sync(0xffffffffu, pn, off);
        ps += __shfl_xor_sync(0xffffffffu, ps, off);
    }
    if (lane == 0) { g_proj[warp] = pn; g_self[warp] = ps; }
}

// ---------------------------------------------------------------------------
// K2: attention aggregation. One warp per node; both steps handled in one
//     32-lane pass (lane<16 = step 0, lane>=16 = step 1); softmax is done
//     independently within each 16-lane half (xor offsets <= 8).
// ---------------------------------------------------------------------------
__global__ void __launch_bounds__(256) att_kernel(
        const float* __restrict__ emb,
        const int*   __restrict__ neighbors,
        const float* __restrict__ fc_b) {
    int warp = (blockIdx.x * blockDim.x + threadIdx.x) >> 5;
    int lane = threadIdx.x & 31;
    if (warp >= N_NODES) return;
    const int node = warp;
    const float fcb   = fc_b[0];
    const float selfv = g_self[node];

    // combined step/neighbor index for this lane
    int s = lane >> 4;            // 0 or 1
    int k = lane & 15;            // 0..15
    int nb = neighbors[(size_t)s * N_NODES * KNB + (size_t)node * KNB + k];

    float sc = g_proj[nb] + selfv + fcb;
    sc = (sc >= 0.f) ? sc : 0.2f * sc;          // leaky relu 0.2

    // softmax within each 16-lane half
    float m = sc;
#pragma unroll
    for (int off = 8; off; off >>= 1)
        m = fmaxf(m, __shfl_xor_sync(0xffffffffu, m, off));
    float ex = __expf(sc - m);
    float ssum = ex;
#pragma unroll
    for (int off = 8; off; off >>= 1)
        ssum += __shfl_xor_sync(0xffffffffu, ssum, off);
    float wgt = ex / ssum;

    // acc starts at (STEPS*K) * own embedding = 32 * emb[node]
    float4 me = reinterpret_cast<const float4*>(emb + (size_t)node * DIM)[lane];
    float4 acc;
    acc.x = 32.f * me.x; acc.y = 32.f * me.y;
    acc.z = 32.f * me.z; acc.w = 32.f * me.w;

    // weighted gather-accumulate over all 32 (step,neighbor) pairs
#pragma unroll
    for (int j = 0; j < 32; j++) {
        float wj = __shfl_sync(0xffffffffu, wgt, j);
        int   ij = __shfl_sync(0xffffffffu, nb,  j);
        float4 v = reinterpret_cast<const float4*>(emb + (size_t)ij * DIM)[lane];
        acc.x += wj * v.x; acc.y += wj * v.y;
        acc.z += wj * v.z; acc.w += wj * v.w;
    }
    reinterpret_cast<float4*>(g_att + (size_t)node * DIM)[lane] = acc;
}

// ---------------------------------------------------------------------------
// K3: per-edge loss partials, 2 edges per warp for MLP, fused final reduce
//     via last-block-done (deterministic fixed-order sums everywhere).
// ---------------------------------------------------------------------------
__global__ void __launch_bounds__(256) edge_kernel(
        const float* __restrict__ emb,
        const int*   __restrict__ edges,
        const int*   __restrict__ labels,
        const float* __restrict__ layer_b,
        float* __restrict__ out) {
    __shared__ float wsum[EDGE_WARPS_PER_BLK];
    __shared__ bool  is_last;
    int warp_in_blk = threadIdx.x >> 5;
    int lane = threadIdx.x & 31;
    int e0 = (blockIdx.x * EDGE_WARPS_PER_BLK + warp_in_blk) * EDGES_PER_WARP;

    // batched upfront loads: 2 edges = int4, 2 labels = int2
    int4 ed = *reinterpret_cast<const int4*>(edges + 2 * e0);   // s0,d0,s1,d1
    int2 lb = *reinterpret_cast<const int2*>(labels + e0);

    const float* base0 = (lb.x == 1) ? g_att : emb;
    const float* base1 = (lb.y == 1) ? g_att : emb;

    // 4 concurrent 512B gathers (high MLP)
    float4 se0 = reinterpret_cast<const float4*>(base0 + (size_t)ed.x * DIM)[lane];
    float4 de0 = reinterpret_cast<const float4*>(base0 + (size_t)ed.y * DIM)[lane];
    float4 se1 = reinterpret_cast<const float4*>(base1 + (size_t)ed.z * DIM)[lane];
    float4 de1 = reinterpret_cast<const float4*>(base1 + (size_t)ed.w * DIM)[lane];

    float4 c0 = reinterpret_cast<const float4*>(g_cw)[lane];
    float4 c1 = reinterpret_cast<const float4*>(g_cw + DIM)[lane];
    float4 b0 = reinterpret_cast<const float4*>(layer_b)[lane];
    float4 b1 = reinterpret_cast<const float4*>(layer_b + DIM)[lane];

    // per-component layer sums: sum_l relu(x*cw[l] + lb[l]); then squared diff
    float a0 = 0.f, a1 = 0.f;
    {
        float t;
        // edge 0
        t = (fmaxf(se0.x*c0.x+b0.x,0.f)+fmaxf(se0.x*c1.x+b1.x,0.f)) - (fmaxf(de0.x*c0.x+b0.x,0.f)+fmaxf(de0.x*c1.x+b1.x,0.f)); a0 += t*t;
        t = (fmaxf(se0.y*c0.y+b0.y,0.f)+fmaxf(se0.y*c1.y+b1.y,0.f)) - (fmaxf(de0.y*c0.y+b0.y,0.f)+fmaxf(de0.y*c1.y+b1.y,0.f)); a0 += t*t;
        t = (fmaxf(se0.z*c0.z+b0.z,0.f)+fmaxf(se0.z*c1.z+b1.z,0.f)) - (fmaxf(de0.z*c0.z+b0.z,0.f)+fmaxf(de0.z*c1.z+b1.z,0.f)); a0 += t*t;
        t = (fmaxf(se0.w*c0.w+b0.w,0.f)+fmaxf(se0.w*c1.w+b1.w,0.f)) - (fmaxf(de0.w*c0.w+b0.w,0.f)+fmaxf(de0.w*c1.w+b1.w,0.f)); a0 += t*t;
        // edge 1
        t = (fmaxf(se1.x*c0.x+b0.x,0.f)+fmaxf(se1.x*c1.x+b1.x,0.f)) - (fmaxf(de1.x*c0.x+b0.x,0.f)+fmaxf(de1.x*c1.x+b1.x,0.f)); a1 += t*t;
        t = (fmaxf(se1.y*c0.y+b0.y,0.f)+fmaxf(se1.y*c1.y+b1.y,0.f)) - (fmaxf(de1.y*c0.y+b0.y,0.f)+fmaxf(de1.y*c1.y+b1.y,0.f)); a1 += t*t;
        t = (fmaxf(se1.z*c0.z+b0.z,0.f)+fmaxf(se1.z*c1.z+b1.z,0.f)) - (fmaxf(de1.z*c0.z+b0.z,0.f)+fmaxf(de1.z*c1.z+b1.z,0.f)); a1 += t*t;
        t = (fmaxf(se1.w*c0.w+b0.w,0.f)+fmaxf(se1.w*c1.w+b1.w,0.f)) - (fmaxf(de1.w*c0.w+b0.w,0.f)+fmaxf(de1.w*c1.w+b1.w,0.f)); a1 += t*t;
    }
#pragma unroll
    for (int off = 16; off; off >>= 1) {
        a0 += __shfl_xor_sync(0xffffffffu, a0, off);
        a1 += __shfl_xor_sync(0xffffffffu, a1, off);
    }
    if (lane == 0) {
        float inv_d = 1.f / (float)DIM;
        float p0 = expf(-a0 * inv_d);
        float p1 = expf(-a1 * inv_d);
        float l0 = (float)lb.x - p0;
        float l1 = (float)lb.y - p1;
        wsum[warp_in_blk] = 0.5f * (l0 * l0 + l1 * l1);
    }
    __syncthreads();
    if (threadIdx.x == 0) {
        float s = 0.f;
#pragma unroll
        for (int i = 0; i < EDGE_WARPS_PER_BLK; i++) s += wsum[i];
        g_partials[blockIdx.x] = s;
        __threadfence();
        int done = atomicAdd(&g_edge_count, 1);
        is_last = (done == EDGE_BLOCKS - 1);
    }
    __syncthreads();

    // last block performs the deterministic final reduction (fixed tree order)
    if (is_last) {
        __shared__ float sh[256];
        __threadfence();  // make other blocks' partials visible
        int t = threadIdx.x;
        float v = 0.f;
#pragma unroll
        for (int i = 0; i < EDGE_BLOCKS / 256; i++)
            v += g_partials[t + i * 256];
        sh[t] = v;
        __syncthreads();
#pragma unroll
        for (int stride = 128; stride; stride >>= 1) {
            if (t < stride) sh[t] += sh[t + stride];
            __syncthreads();
        }
        if (t == 0) out[0] = sh[0];
    }
}

// ---------------------------------------------------------------------------
// Inputs (metadata order): 0 edges(i32 E*2), 1 labels(i32 E), 2 neighbors(i32
// STEPS*N*K), 3 embeddings(f32 N*D), 4 fc_w(f32 2D), 5 fc_b(f32 1),
// 6 layer_w(f32 L*D*D), 7 layer_b(f32 L*D). Output: f32 scalar.
// ---------------------------------------------------------------------------
extern "C" void kernel_launch(void* const* d_in, const int* in_sizes, int n_in,
                              void* d_out, int out_size) {
    const int*   edges     = (const int*)  d_in[0];
    const int*   labels    = (const int*)  d_in[1];
    const int*   neighbors = (const int*)  d_in[2];
    const float* emb       = (const float*)d_in[3];
    const float* fc_w      = (const float*)d_in[4];
    const float* fc_b      = (const float*)d_in[5];
    const float* layer_w   = (const float*)d_in[6];
    const float* layer_b   = (const float*)d_in[7];
    float* out = (float*)d_out;

    const int warps_per_blk = 8;                       // 256 threads
    int node_blocks = (N_NODES + warps_per_blk - 1) / warps_per_blk;  // 2500

    proj_cw_kernel<<<node_blocks, 256>>>(emb, fc_w, layer_w);
    att_kernel<<<node_blocks, 256>>>(emb, neighbors, fc_b);
    edge_kernel<<<EDGE_BLOCKS, 256>>>(emb, edges, labels, layer_b, out);
}

// round 5
// speedup vs baseline: 1.0745x; 1.0058x over previous
#include <cuda_runtime.h>
#include <math.h>

#define N_NODES 20000
#define DIM 128
#define KNB 16
#define STEPS 2
#define LAYERS 2
#define E_EDGES 8192
#define EDGES_PER_WARP 2
#define EDGE_WARPS_PER_BLK 8
#define EDGE_BLOCKS (E_EDGES / (EDGES_PER_WARP * EDGE_WARPS_PER_BLK))  // 512

#define NODES_PER_WARP 4
#define PROJ_WARPS_PER_BLK 8
#define PROJ_BLOCKS (N_NODES / (NODES_PER_WARP * PROJ_WARPS_PER_BLK))  // 625

// Scratch (static __device__ — no allocations allowed)
__device__ float g_proj[N_NODES];
__device__ float g_self[N_NODES];
__device__ float g_att[N_NODES * DIM];
__device__ float g_cw[LAYERS * DIM];
__device__ float g_partials[EDGE_BLOCKS];
__device__ int   g_edge_count;

// ---------------------------------------------------------------------------
// K1: fused — proj[n] = emb[n]·w_n, self[n] = emb[n]·w_s.
//     4 nodes per warp with batched loads (MLP=4) to hide DRAM latency.
//     Block 0 additionally computes cw[l,d] = sum_f layer_w[l,f,d]
//     and resets the edge completion counter for this graph replay.
// ---------------------------------------------------------------------------
__global__ void __launch_bounds__(256) proj_cw_kernel(
        const float* __restrict__ emb,
        const float* __restrict__ fc_w,
        const float* __restrict__ layer_w) {
    // --- cw + counter reset on block 0 (tiny extra work) ---
    if (blockIdx.x == 0) {
        int t = threadIdx.x;                      // 0..255 == LAYERS*DIM
        int l = t >> 7, d = t & 127;
        const float* w = layer_w + l * DIM * DIM + d;
        float s = 0.f;
#pragma unroll 16
        for (int f = 0; f < DIM; f++) s += w[f * DIM];
        g_cw[t] = s;
        if (t == 0) g_edge_count = 0;
    }

    int warp = (blockIdx.x * blockDim.x + threadIdx.x) >> 5;
    int lane = threadIdx.x & 31;
    int n0 = warp * NODES_PER_WARP;
    if (n0 >= N_NODES) return;

    float4 wn = reinterpret_cast<const float4*>(fc_w)[lane];
    float4 ws = reinterpret_cast<const float4*>(fc_w + DIM)[lane];

    // 4 independent 512B row loads in flight simultaneously
    float4 e0 = reinterpret_cast<const float4*>(emb + (size_t)(n0 + 0) * DIM)[lane];
    float4 e1 = reinterpret_cast<const float4*>(emb + (size_t)(n0 + 1) * DIM)[lane];
    float4 e2 = reinterpret_cast<const float4*>(emb + (size_t)(n0 + 2) * DIM)[lane];
    float4 e3 = reinterpret_cast<const float4*>(emb + (size_t)(n0 + 3) * DIM)[lane];

    float pn0 = e0.x*wn.x + e0.y*wn.y + e0.z*wn.z + e0.w*wn.w;
    float ps0 = e0.x*ws.x + e0.y*ws.y + e0.z*ws.z + e0.w*ws.w;
    float pn1 = e1.x*wn.x + e1.y*wn.y + e1.z*wn.z + e1.w*wn.w;
    float ps1 = e1.x*ws.x + e1.y*ws.y + e1.z*ws.z + e1.w*ws.w;
    float pn2 = e2.x*wn.x + e2.y*wn.y + e2.z*wn.z + e2.w*wn.w;
    float ps2 = e2.x*ws.x + e2.y*ws.y + e2.z*ws.z + e2.w*ws.w;
    float pn3 = e3.x*wn.x + e3.y*wn.y + e3.z*wn.z + e3.w*wn.w;
    float ps3 = e3.x*ws.x + e3.y*ws.y + e3.z*ws.z + e3.w*ws.w;

#pragma unroll
    for (int off = 16; off; off >>= 1) {
        pn0 += __shfl_xor_sync(0xffffffffu, pn0, off);
        ps0 += __shfl_xor_sync(0xffffffffu, ps0, off);
        pn1 += __shfl_xor_sync(0xffffffffu, pn1, off);
        ps1 += __shfl_xor_sync(0xffffffffu, ps1, off);
        pn2 += __shfl_xor_sync(0xffffffffu, pn2, off);
        ps2 += __shfl_xor_sync(0xffffffffu, ps2, off);
        pn3 += __shfl_xor_sync(0xffffffffu, pn3, off);
        ps3 += __shfl_xor_sync(0xffffffffu, ps3, off);
    }
    if (lane == 0) {
        g_proj[n0 + 0] = pn0; g_self[n0 + 0] = ps0;
        g_proj[n0 + 1] = pn1; g_self[n0 + 1] = ps1;
        g_proj[n0 + 2] = pn2; g_self[n0 + 2] = ps2;
        g_proj[n0 + 3] = pn3; g_self[n0 + 3] = ps3;
    }
}

// ---------------------------------------------------------------------------
// K2: attention aggregation. One warp per node; both steps handled in one
//     32-lane pass (lane<16 = step 0, lane>=16 = step 1); softmax is done
//     independently within each 16-lane half (xor offsets <= 8).
// ---------------------------------------------------------------------------
__global__ void __launch_bounds__(256) att_kernel(
        const float* __restrict__ emb,
        const int*   __restrict__ neighbors,
        const float* __restrict__ fc_b) {
    int warp = (blockIdx.x * blockDim.x + threadIdx.x) >> 5;
    int lane = threadIdx.x & 31;
    if (warp >= N_NODES) return;
    const int node = warp;
    const float fcb   = fc_b[0];
    const float selfv = g_self[node];

    // combined step/neighbor index for this lane
    int s = lane >> 4;            // 0 or 1
    int k = lane & 15;            // 0..15
    int nb = neighbors[(size_t)s * N_NODES * KNB + (size_t)node * KNB + k];

    float sc = g_proj[nb] + selfv + fcb;
    sc = (sc >= 0.f) ? sc : 0.2f * sc;          // leaky relu 0.2

    // softmax within each 16-lane half
    float m = sc;
#pragma unroll
    for (int off = 8; off; off >>= 1)
        m = fmaxf(m, __shfl_xor_sync(0xffffffffu, m, off));
    float ex = __expf(sc - m);
    float ssum = ex;
#pragma unroll
    for (int off = 8; off; off >>= 1)
        ssum += __shfl_xor_sync(0xffffffffu, ssum, off);
    float wgt = ex / ssum;

    // acc starts at (STEPS*K) * own embedding = 32 * emb[node]
    float4 me = reinterpret_cast<const float4*>(emb + (size_t)node * DIM)[lane];
    float4 acc;
    acc.x = 32.f * me.x; acc.y = 32.f * me.y;
    acc.z = 32.f * me.z; acc.w = 32.f * me.w;

    // weighted gather-accumulate over all 32 (step,neighbor) pairs
#pragma unroll
    for (int j = 0; j < 32; j++) {
        float wj = __shfl_sync(0xffffffffu, wgt, j);
        int   ij = __shfl_sync(0xffffffffu, nb,  j);
        float4 v = reinterpret_cast<const float4*>(emb + (size_t)ij * DIM)[lane];
        acc.x += wj * v.x; acc.y += wj * v.y;
        acc.z += wj * v.z; acc.w += wj * v.w;
    }
    reinterpret_cast<float4*>(g_att + (size_t)node * DIM)[lane] = acc;
}

// ---------------------------------------------------------------------------
// K3: per-edge loss partials, 2 edges per warp for MLP, fused final reduce
//     via last-block-done (deterministic fixed-order sums everywhere).
// ---------------------------------------------------------------------------
__global__ void __launch_bounds__(256) edge_kernel(
        const float* __restrict__ emb,
        const int*   __restrict__ edges,
        const int*   __restrict__ labels,
        const float* __restrict__ layer_b,
        float* __restrict__ out) {
    __shared__ float wsum[EDGE_WARPS_PER_BLK];
    __shared__ bool  is_last;
    int warp_in_blk = threadIdx.x >> 5;
    int lane = threadIdx.x & 31;
    int e0 = (blockIdx.x * EDGE_WARPS_PER_BLK + warp_in_blk) * EDGES_PER_WARP;

    // batched upfront loads: 2 edges = int4, 2 labels = int2
    int4 ed = *reinterpret_cast<const int4*>(edges + 2 * e0);   // s0,d0,s1,d1
    int2 lb = *reinterpret_cast<const int2*>(labels + e0);

    const float* base0 = (lb.x == 1) ? g_att : emb;
    const float* base1 = (lb.y == 1) ? g_att : emb;

    // 4 concurrent 512B gathers (high MLP)
    float4 se0 = reinterpret_cast<const float4*>(base0 + (size_t)ed.x * DIM)[lane];
    float4 de0 = reinterpret_cast<const float4*>(base0 + (size_t)ed.y * DIM)[lane];
    float4 se1 = reinterpret_cast<const float4*>(base1 + (size_t)ed.z * DIM)[lane];
    float4 de1 = reinterpret_cast<const float4*>(base1 + (size_t)ed.w * DIM)[lane];

    float4 c0 = reinterpret_cast<const float4*>(g_cw)[lane];
    float4 c1 = reinterpret_cast<const float4*>(g_cw + DIM)[lane];
    float4 b0 = reinterpret_cast<const float4*>(layer_b)[lane];
    float4 b1 = reinterpret_cast<const float4*>(layer_b + DIM)[lane];

    // per-component layer sums: sum_l relu(x*cw[l] + lb[l]); then squared diff
    float a0 = 0.f, a1 = 0.f;
    {
        float t;
        // edge 0
        t = (fmaxf(se0.x*c0.x+b0.x,0.f)+fmaxf(se0.x*c1.x+b1.x,0.f)) - (fmaxf(de0.x*c0.x+b0.x,0.f)+fmaxf(de0.x*c1.x+b1.x,0.f)); a0 += t*t;
        t = (fmaxf(se0.y*c0.y+b0.y,0.f)+fmaxf(se0.y*c1.y+b1.y,0.f)) - (fmaxf(de0.y*c0.y+b0.y,0.f)+fmaxf(de0.y*c1.y+b1.y,0.f)); a0 += t*t;
        t = (fmaxf(se0.z*c0.z+b0.z,0.f)+fmaxf(se0.z*c1.z+b1.z,0.f)) - (fmaxf(de0.z*c0.z+b0.z,0.f)+fmaxf(de0.z*c1.z+b1.z,0.f)); a0 += t*t;
        t = (fmaxf(se0.w*c0.w+b0.w,0.f)+fmaxf(se0.w*c1.w+b1.w,0.f)) - (fmaxf(de0.w*c0.w+b0.w,0.f)+fmaxf(de0.w*c1.w+b1.w,0.f)); a0 += t*t;
        // edge 1
        t = (fmaxf(se1.x*c0.x+b0.x,0.f)+fmaxf(se1.x*c1.x+b1.x,0.f)) - (fmaxf(de1.x*c0.x+b0.x,0.f)+fmaxf(de1.x*c1.x+b1.x,0.f)); a1 += t*t;
        t = (fmaxf(se1.y*c0.y+b0.y,0.f)+fmaxf(se1.y*c1.y+b1.y,0.f)) - (fmaxf(de1.y*c0.y+b0.y,0.f)+fmaxf(de1.y*c1.y+b1.y,0.f)); a1 += t*t;
        t = (fmaxf(se1.z*c0.z+b0.z,0.f)+fmaxf(se1.z*c1.z+b1.z,0.f)) - (fmaxf(de1.z*c0.z+b0.z,0.f)+fmaxf(de1.z*c1.z+b1.z,0.f)); a1 += t*t;
        t = (fmaxf(se1.w*c0.w+b0.w,0.f)+fmaxf(se1.w*c1.w+b1.w,0.f)) - (fmaxf(de1.w*c0.w+b0.w,0.f)+fmaxf(de1.w*c1.w+b1.w,0.f)); a1 += t*t;
    }
#pragma unroll
    for (int off = 16; off; off >>= 1) {
        a0 += __shfl_xor_sync(0xffffffffu, a0, off);
        a1 += __shfl_xor_sync(0xffffffffu, a1, off);
    }
    if (lane == 0) {
        float inv_d = 1.f / (float)DIM;
        float p0 = expf(-a0 * inv_d);
        float p1 = expf(-a1 * inv_d);
        float l0 = (float)lb.x - p0;
        float l1 = (float)lb.y - p1;
        wsum[warp_in_blk] = 0.5f * (l0 * l0 + l1 * l1);
    }
    __syncthreads();
    if (threadIdx.x == 0) {
        float s = 0.f;
#pragma unroll
        for (int i = 0; i < EDGE_WARPS_PER_BLK; i++) s += wsum[i];
        g_partials[blockIdx.x] = s;
        __threadfence();
        int done = atomicAdd(&g_edge_count, 1);
        is_last = (done == EDGE_BLOCKS - 1);
    }
    __syncthreads();

    // last block performs the deterministic final reduction (fixed tree order)
    if (is_last) {
        __shared__ float sh[256];
        __threadfence();  // make other blocks' partials visible
        int t = threadIdx.x;
        float v = 0.f;
#pragma unroll
        for (int i = 0; i < EDGE_BLOCKS / 256; i++)
            v += g_partials[t + i * 256];
        sh[t] = v;
        __syncthreads();
#pragma unroll
        for (int stride = 128; stride; stride >>= 1) {
            if (t < stride) sh[t] += sh[t + stride];
            __syncthreads();
        }
        if (t == 0) out[0] = sh[0];
    }
}

// ---------------------------------------------------------------------------
// Inputs (metadata order): 0 edges(i32 E*2), 1 labels(i32 E), 2 neighbors(i32
// STEPS*N*K), 3 embeddings(f32 N*D), 4 fc_w(f32 2D), 5 fc_b(f32 1),
// 6 layer_w(f32 L*D*D), 7 layer_b(f32 L*D). Output: f32 scalar.
// ---------------------------------------------------------------------------
extern "C" void kernel_launch(void* const* d_in, const int* in_sizes, int n_in,
                              void* d_out, int out_size) {
    const int*   edges     = (const int*)  d_in[0];
    const int*   labels    = (const int*)  d_in[1];
    const int*   neighbors = (const int*)  d_in[2];
    const float* emb       = (const float*)d_in[3];
    const float* fc_w      = (const float*)d_in[4];
    const float* fc_b      = (const float*)d_in[5];
    const float* layer_w   = (const float*)d_in[6];
    const float* layer_b   = (const float*)d_in[7];
    float* out = (float*)d_out;

    int att_blocks = (N_NODES + 7) / 8;   // 8 warps/block -> 2500

    proj_cw_kernel<<<PROJ_BLOCKS, 256>>>(emb, fc_w, layer_w);
    att_kernel<<<att_blocks, 256>>>(emb, neighbors, fc_b);
    edge_kernel<<<EDGE_BLOCKS, 256>>>(emb, edges, labels, layer_b, out);
}

// round 6
// speedup vs baseline: 1.2182x; 1.1338x over previous
#include <cuda_runtime.h>
#include <cuda_bf16.h>
#include <math.h>

#define N_NODES 20000
#define DIM 128
#define KNB 16
#define STEPS 2
#define LAYERS 2
#define E_EDGES 8192
#define EDGES_PER_WARP 2
#define EDGE_WARPS_PER_BLK 8
#define EDGE_BLOCKS (E_EDGES / (EDGES_PER_WARP * EDGE_WARPS_PER_BLK))  // 512

#define NODES_PER_WARP 4
#define PROJ_BLOCKS (N_NODES / (NODES_PER_WARP * 8))  // 625

// Scratch (static __device__ — no allocations allowed)
__device__ float g_proj[N_NODES];
__device__ float g_self[N_NODES];
__device__ float g_att[N_NODES * DIM];
__device__ float g_cw[LAYERS * DIM];
__device__ float g_partials[EDGE_BLOCKS];
__device__ int   g_edge_count;
// bf16 copy of embeddings: 128 bf16 per row = 32 uint2 per row (5.12 MB)
__device__ uint2 g_embh[N_NODES * 32];

// ---------------------------------------------------------------------------
// K1: fused — proj[n] = emb[n]·w_n, self[n] = emb[n]·w_s, plus bf16 copy of
//     emb (rows already in registers). Block 0 additionally computes
//     cw[l,d] = sum_f layer_w[l,f,d] and resets the edge counter.
// ---------------------------------------------------------------------------
__global__ void __launch_bounds__(256) proj_cw_kernel(
        const float* __restrict__ emb,
        const float* __restrict__ fc_w,
        const float* __restrict__ layer_w) {
    if (blockIdx.x == 0) {
        int t = threadIdx.x;                      // 0..255 == LAYERS*DIM
        int l = t >> 7, d = t & 127;
        const float* w = layer_w + l * DIM * DIM + d;
        float s = 0.f;
#pragma unroll 16
        for (int f = 0; f < DIM; f++) s += w[f * DIM];
        g_cw[t] = s;
        if (t == 0) g_edge_count = 0;
    }

    int warp = (blockIdx.x * blockDim.x + threadIdx.x) >> 5;
    int lane = threadIdx.x & 31;
    int n0 = warp * NODES_PER_WARP;
    if (n0 >= N_NODES) return;

    float4 wn = reinterpret_cast<const float4*>(fc_w)[lane];
    float4 ws = reinterpret_cast<const float4*>(fc_w + DIM)[lane];

    // 4 independent 512B row loads in flight simultaneously
    float4 e0 = reinterpret_cast<const float4*>(emb + (size_t)(n0 + 0) * DIM)[lane];
    float4 e1 = reinterpret_cast<const float4*>(emb + (size_t)(n0 + 1) * DIM)[lane];
    float4 e2 = reinterpret_cast<const float4*>(emb + (size_t)(n0 + 2) * DIM)[lane];
    float4 e3 = reinterpret_cast<const float4*>(emb + (size_t)(n0 + 3) * DIM)[lane];

    // bf16 copy (round-to-nearest), coalesced 256B stores
    {
        __nv_bfloat162 h00 = __floats2bfloat162_rn(e0.x, e0.y);
        __nv_bfloat162 h01 = __floats2bfloat162_rn(e0.z, e0.w);
        __nv_bfloat162 h10 = __floats2bfloat162_rn(e1.x, e1.y);
        __nv_bfloat162 h11 = __floats2bfloat162_rn(e1.z, e1.w);
        __nv_bfloat162 h20 = __floats2bfloat162_rn(e2.x, e2.y);
        __nv_bfloat162 h21 = __floats2bfloat162_rn(e2.z, e2.w);
        __nv_bfloat162 h30 = __floats2bfloat162_rn(e3.x, e3.y);
        __nv_bfloat162 h31 = __floats2bfloat162_rn(e3.z, e3.w);
        g_embh[(size_t)(n0 + 0) * 32 + lane] =
            make_uint2(*(unsigned*)&h00, *(unsigned*)&h01);
        g_embh[(size_t)(n0 + 1) * 32 + lane] =
            make_uint2(*(unsigned*)&h10, *(unsigned*)&h11);
        g_embh[(size_t)(n0 + 2) * 32 + lane] =
            make_uint2(*(unsigned*)&h20, *(unsigned*)&h21);
        g_embh[(size_t)(n0 + 3) * 32 + lane] =
            make_uint2(*(unsigned*)&h30, *(unsigned*)&h31);
    }

    float pn0 = e0.x*wn.x + e0.y*wn.y + e0.z*wn.z + e0.w*wn.w;
    float ps0 = e0.x*ws.x + e0.y*ws.y + e0.z*ws.z + e0.w*ws.w;
    float pn1 = e1.x*wn.x + e1.y*wn.y + e1.z*wn.z + e1.w*wn.w;
    float ps1 = e1.x*ws.x + e1.y*ws.y + e1.z*ws.z + e1.w*ws.w;
    float pn2 = e2.x*wn.x + e2.y*wn.y + e2.z*wn.z + e2.w*wn.w;
    float ps2 = e2.x*ws.x + e2.y*ws.y + e2.z*ws.z + e2.w*ws.w;
    float pn3 = e3.x*wn.x + e3.y*wn.y + e3.z*wn.z + e3.w*wn.w;
    float ps3 = e3.x*ws.x + e3.y*ws.y + e3.z*ws.z + e3.w*ws.w;

#pragma unroll
    for (int off = 16; off; off >>= 1) {
        pn0 += __shfl_xor_sync(0xffffffffu, pn0, off);
        ps0 += __shfl_xor_sync(0xffffffffu, ps0, off);
        pn1 += __shfl_xor_sync(0xffffffffu, pn1, off);
        ps1 += __shfl_xor_sync(0xffffffffu, ps1, off);
        pn2 += __shfl_xor_sync(0xffffffffu, pn2, off);
        ps2 += __shfl_xor_sync(0xffffffffu, ps2, off);
        pn3 += __shfl_xor_sync(0xffffffffu, pn3, off);
        ps3 += __shfl_xor_sync(0xffffffffu, ps3, off);
    }
    if (lane == 0) {
        g_proj[n0 + 0] = pn0; g_self[n0 + 0] = ps0;
        g_proj[n0 + 1] = pn1; g_self[n0 + 1] = ps1;
        g_proj[n0 + 2] = pn2; g_self[n0 + 2] = ps2;
        g_proj[n0 + 3] = pn3; g_self[n0 + 3] = ps3;
    }
}

// ---------------------------------------------------------------------------
// K2: attention aggregation. One warp per node; lane<16 = step 0,
//     lane>=16 = step 1; softmax within each 16-lane half.
//     Neighbor rows gathered in bf16 (halves L2 traffic); self term fp32.
// ---------------------------------------------------------------------------
__global__ void __launch_bounds__(256) att_kernel(
        const float* __restrict__ emb,
        const int*   __restrict__ neighbors,
        const float* __restrict__ fc_b) {
    int warp = (blockIdx.x * blockDim.x + threadIdx.x) >> 5;
    int lane = threadIdx.x & 31;
    if (warp >= N_NODES) return;
    const int node = warp;
    const float fcb   = fc_b[0];
    const float selfv = g_self[node];

    int s = lane >> 4;            // 0 or 1
    int k = lane & 15;            // 0..15
    int nb = neighbors[(size_t)s * N_NODES * KNB + (size_t)node * KNB + k];

    float sc = g_proj[nb] + selfv + fcb;
    sc = (sc >= 0.f) ? sc : 0.2f * sc;          // leaky relu 0.2

    float m = sc;
#pragma unroll
    for (int off = 8; off; off >>= 1)
        m = fmaxf(m, __shfl_xor_sync(0xffffffffu, m, off));
    float ex = __expf(sc - m);
    float ssum = ex;
#pragma unroll
    for (int off = 8; off; off >>= 1)
        ssum += __shfl_xor_sync(0xffffffffu, ssum, off);
    float wgt = ex / ssum;

    // acc starts at (STEPS*K) * own embedding = 32 * emb[node]  (exact fp32)
    float4 me = reinterpret_cast<const float4*>(emb + (size_t)node * DIM)[lane];
    float4 acc;
    acc.x = 32.f * me.x; acc.y = 32.f * me.y;
    acc.z = 32.f * me.z; acc.w = 32.f * me.w;

    // weighted gather-accumulate over all 32 (step,neighbor) pairs, bf16 rows
#pragma unroll
    for (int j = 0; j < 32; j++) {
        float wj = __shfl_sync(0xffffffffu, wgt, j);
        int   ij = __shfl_sync(0xffffffffu, nb,  j);
        uint2 u = g_embh[(size_t)ij * 32 + lane];
        float2 f0 = __bfloat1622float2(*reinterpret_cast<__nv_bfloat162*>(&u.x));
        float2 f1 = __bfloat1622float2(*reinterpret_cast<__nv_bfloat162*>(&u.y));
        acc.x += wj * f0.x; acc.y += wj * f0.y;
        acc.z += wj * f1.x; acc.w += wj * f1.y;
    }
    reinterpret_cast<float4*>(g_att + (size_t)node * DIM)[lane] = acc;
}

// ---------------------------------------------------------------------------
// K3: per-edge loss partials, 2 edges per warp, fused deterministic reduce.
// ---------------------------------------------------------------------------
__global__ void __launch_bounds__(256) edge_kernel(
        const float* __restrict__ emb,
        const int*   __restrict__ edges,
        const int*   __restrict__ labels,
        const float* __restrict__ layer_b,
        float* __restrict__ out) {
    __shared__ float wsum[EDGE_WARPS_PER_BLK];
    __shared__ bool  is_last;
    int warp_in_blk = threadIdx.x >> 5;
    int lane = threadIdx.x & 31;
    int e0 = (blockIdx.x * EDGE_WARPS_PER_BLK + warp_in_blk) * EDGES_PER_WARP;

    int4 ed = *reinterpret_cast<const int4*>(edges + 2 * e0);   // s0,d0,s1,d1
    int2 lb = *reinterpret_cast<const int2*>(labels + e0);

    const float* base0 = (lb.x == 1) ? g_att : emb;
    const float* base1 = (lb.y == 1) ? g_att : emb;

    float4 se0 = reinterpret_cast<const float4*>(base0 + (size_t)ed.x * DIM)[lane];
    float4 de0 = reinterpret_cast<const float4*>(base0 + (size_t)ed.y * DIM)[lane];
    float4 se1 = reinterpret_cast<const float4*>(base1 + (size_t)ed.z * DIM)[lane];
    float4 de1 = reinterpret_cast<const float4*>(base1 + (size_t)ed.w * DIM)[lane];

    float4 c0 = reinterpret_cast<const float4*>(g_cw)[lane];
    float4 c1 = reinterpret_cast<const float4*>(g_cw + DIM)[lane];
    float4 b0 = reinterpret_cast<const float4*>(layer_b)[lane];
    float4 b1 = reinterpret_cast<const float4*>(layer_b + DIM)[lane];

    float a0 = 0.f, a1 = 0.f;
    {
        float t;
        t = (fmaxf(se0.x*c0.x+b0.x,0.f)+fmaxf(se0.x*c1.x+b1.x,0.f)) - (fmaxf(de0.x*c0.x+b0.x,0.f)+fmaxf(de0.x*c1.x+b1.x,0.f)); a0 += t*t;
        t = (fmaxf(se0.y*c0.y+b0.y,0.f)+fmaxf(se0.y*c1.y+b1.y,0.f)) - (fmaxf(de0.y*c0.y+b0.y,0.f)+fmaxf(de0.y*c1.y+b1.y,0.f)); a0 += t*t;
        t = (fmaxf(se0.z*c0.z+b0.z,0.f)+fmaxf(se0.z*c1.z+b1.z,0.f)) - (fmaxf(de0.z*c0.z+b0.z,0.f)+fmaxf(de0.z*c1.z+b1.z,0.f)); a0 += t*t;
        t = (fmaxf(se0.w*c0.w+b0.w,0.f)+fmaxf(se0.w*c1.w+b1.w,0.f)) - (fmaxf(de0.w*c0.w+b0.w,0.f)+fmaxf(de0.w*c1.w+b1.w,0.f)); a0 += t*t;
        t = (fmaxf(se1.x*c0.x+b0.x,0.f)+fmaxf(se1.x*c1.x+b1.x,0.f)) - (fmaxf(de1.x*c0.x+b0.x,0.f)+fmaxf(de1.x*c1.x+b1.x,0.f)); a1 += t*t;
        t = (fmaxf(se1.y*c0.y+b0.y,0.f)+fmaxf(se1.y*c1.y+b1.y,0.f)) - (fmaxf(de1.y*c0.y+b0.y,0.f)+fmaxf(de1.y*c1.y+b1.y,0.f)); a1 += t*t;
        t = (fmaxf(se1.z*c0.z+b0.z,0.f)+fmaxf(se1.z*c1.z+b1.z,0.f)) - (fmaxf(de1.z*c0.z+b0.z,0.f)+fmaxf(de1.z*c1.z+b1.z,0.f)); a1 += t*t;
        t = (fmaxf(se1.w*c0.w+b0.w,0.f)+fmaxf(se1.w*c1.w+b1.w,0.f)) - (fmaxf(de1.w*c0.w+b0.w,0.f)+fmaxf(de1.w*c1.w+b1.w,0.f)); a1 += t*t;
    }
#pragma unroll
    for (int off = 16; off; off >>= 1) {
        a0 += __shfl_xor_sync(0xffffffffu, a0, off);
        a1 += __shfl_xor_sync(0xffffffffu, a1, off);
    }
    if (lane == 0) {
        float inv_d = 1.f / (float)DIM;
        float p0 = expf(-a0 * inv_d);
        float p1 = expf(-a1 * inv_d);
        float l0 = (float)lb.x - p0;
        float l1 = (float)lb.y - p1;
        wsum[warp_in_blk] = 0.5f * (l0 * l0 + l1 * l1);
    }
    __syncthreads();
    if (threadIdx.x == 0) {
        float s = 0.f;
#pragma unroll
        for (int i = 0; i < EDGE_WARPS_PER_BLK; i++) s += wsum[i];
        g_partials[blockIdx.x] = s;
        __threadfence();
        int done = atomicAdd(&g_edge_count, 1);
        is_last = (done == EDGE_BLOCKS - 1);
    }
    __syncthreads();

    if (is_last) {
        __shared__ float sh[256];
        __threadfence();
        int t = threadIdx.x;
        float v = 0.f;
#pragma unroll
        for (int i = 0; i < EDGE_BLOCKS / 256; i++)
            v += g_partials[t + i * 256];
        sh[t] = v;
        __syncthreads();
#pragma unroll
        for (int stride = 128; stride; stride >>= 1) {
            if (t < stride) sh[t] += sh[t + stride];
            __syncthreads();
        }
        if (t == 0) out[0] = sh[0];
    }
}

// ---------------------------------------------------------------------------
extern "C" void kernel_launch(void* const* d_in, const int* in_sizes, int n_in,
                              void* d_out, int out_size) {
    const int*   edges     = (const int*)  d_in[0];
    const int*   labels    = (const int*)  d_in[1];
    const int*   neighbors = (const int*)  d_in[2];
    const float* emb       = (const float*)d_in[3];
    const float* fc_w      = (const float*)d_in[4];
    const float* fc_b      = (const float*)d_in[5];
    const float* layer_w   = (const float*)d_in[6];
    const float* layer_b   = (const float*)d_in[7];
    float* out = (float*)d_out;

    int att_blocks = (N_NODES + 7) / 8;   // 8 warps/block -> 2500

    proj_cw_kernel<<<PROJ_BLOCKS, 256>>>(emb, fc_w, layer_w);
    att_kernel<<<att_blocks, 256>>>(emb, neighbors, fc_b);
    edge_kernel<<<EDGE_BLOCKS, 256>>>(emb, edges, labels, layer_b, out);
}

// round 7
// speedup vs baseline: 1.5452x; 1.2684x over previous
#include <cuda_runtime.h>
#include <cuda_bf16.h>
#include <cuda_fp8.h>
#include <math.h>

#define N_NODES 20000
#define DIM 128
#define KNB 16
#define STEPS 2
#define LAYERS 2
#define E_EDGES 8192
#define EDGES_PER_WARP 2
#define EDGE_WARPS_PER_BLK 8
#define EDGE_BLOCKS (E_EDGES / (EDGES_PER_WARP * EDGE_WARPS_PER_BLK))  // 512

#define PROJ_NODES_PER_WARP 2
#define PROJ_BLOCKS (N_NODES / (PROJ_NODES_PER_WARP * 8))  // 1250

#define MAX_LIST (2 * E_EDGES)            // 16384 worst case
#define ATT_BLOCKS (MAX_LIST / 8)         // 2048 blocks, 8 warps each

// Scratch (static __device__ — no allocations allowed)
__device__ float    g_proj[N_NODES];
__device__ float    g_self[N_NODES];
__device__ float    g_att[N_NODES * DIM];
__device__ float    g_cw[LAYERS * DIM];
__device__ float    g_partials[EDGE_BLOCKS];
__device__ int      g_edge_count;
__device__ int      g_list_count;
__device__ int      g_list[MAX_LIST];
// fp8 e4m3 copy of embeddings: 128 fp8 per row = 32 uint per row (2.56 MB)
__device__ unsigned g_emb8[N_NODES * 32];

__device__ __forceinline__ float2 fp8x2_to_float2(unsigned short v) {
    __half2_raw hr = __nv_cvt_fp8x2_to_halfraw2((__nv_fp8x2_storage_t)v, __NV_E4M3);
    __half2 h = *reinterpret_cast<__half2*>(&hr);
    return __half22float2(h);
}

// ---------------------------------------------------------------------------
// K1: fused — proj[n] = emb[n]·w_n, self[n] = emb[n]·w_s, plus fp8 copy of
//     emb. 2 nodes per warp (MLP=2, full occupancy at 1250 blocks).
//     Block 0 additionally computes cw[l,d] = sum_f layer_w[l,f,d] and
//     resets the edge/list counters for this graph replay.
// ---------------------------------------------------------------------------
__global__ void __launch_bounds__(256) proj_cw_kernel(
        const float* __restrict__ emb,
        const float* __restrict__ fc_w,
        const float* __restrict__ layer_w) {
    if (blockIdx.x == 0) {
        int t = threadIdx.x;                      // 0..255 == LAYERS*DIM
        int l = t >> 7, d = t & 127;
        const float* w = layer_w + l * DIM * DIM + d;
        float s = 0.f;
#pragma unroll 16
        for (int f = 0; f < DIM; f++) s += w[f * DIM];
        g_cw[t] = s;
        if (t == 0) { g_edge_count = 0; g_list_count = 0; }
    }

    int warp = (blockIdx.x * blockDim.x + threadIdx.x) >> 5;
    int lane = threadIdx.x & 31;
    int n0 = warp * PROJ_NODES_PER_WARP;
    if (n0 >= N_NODES) return;

    float4 wn = reinterpret_cast<const float4*>(fc_w)[lane];
    float4 ws = reinterpret_cast<const float4*>(fc_w + DIM)[lane];

    // 2 independent 512B row loads in flight
    float4 e0 = reinterpret_cast<const float4*>(emb + (size_t)(n0 + 0) * DIM)[lane];
    float4 e1 = reinterpret_cast<const float4*>(emb + (size_t)(n0 + 1) * DIM)[lane];

    // fp8 e4m3 copy (coalesced 128B row stores)
    {
        __nv_fp8x4_e4m3 p0(e0);
        __nv_fp8x4_e4m3 p1(e1);
        g_emb8[(size_t)(n0 + 0) * 32 + lane] = *reinterpret_cast<unsigned*>(&p0);
        g_emb8[(size_t)(n0 + 1) * 32 + lane] = *reinterpret_cast<unsigned*>(&p1);
    }

    float pn0 = e0.x*wn.x + e0.y*wn.y + e0.z*wn.z + e0.w*wn.w;
    float ps0 = e0.x*ws.x + e0.y*ws.y + e0.z*ws.z + e0.w*ws.w;
    float pn1 = e1.x*wn.x + e1.y*wn.y + e1.z*wn.z + e1.w*wn.w;
    float ps1 = e1.x*ws.x + e1.y*ws.y + e1.z*ws.z + e1.w*ws.w;

#pragma unroll
    for (int off = 16; off; off >>= 1) {
        pn0 += __shfl_xor_sync(0xffffffffu, pn0, off);
        ps0 += __shfl_xor_sync(0xffffffffu, ps0, off);
        pn1 += __shfl_xor_sync(0xffffffffu, pn1, off);
        ps1 += __shfl_xor_sync(0xffffffffu, ps1, off);
    }
    if (lane == 0) {
        g_proj[n0 + 0] = pn0; g_self[n0 + 0] = ps0;
        g_proj[n0 + 1] = pn1; g_self[n0 + 1] = ps1;
    }
}

// ---------------------------------------------------------------------------
// K1b: mark — append both endpoints of every label==1 edge to g_list.
//      Duplicates allowed (att writes are idempotent -> deterministic).
// ---------------------------------------------------------------------------
__global__ void __launch_bounds__(256) mark_kernel(
        const int* __restrict__ edges,
        const int* __restrict__ labels) {
    int e = blockIdx.x * blockDim.x + threadIdx.x;
    if (e >= E_EDGES) return;
    if (labels[e] == 1) {
        int2 ed = *reinterpret_cast<const int2*>(edges + 2 * e);
        int pos = atomicAdd(&g_list_count, 2);
        g_list[pos]     = ed.x;
        g_list[pos + 1] = ed.y;
    }
}

// ---------------------------------------------------------------------------
// K2: attention aggregation over the label-1 endpoint list only.
//     One warp per list entry; lane<16 = step 0, lane>=16 = step 1;
//     softmax within each 16-lane half. Neighbor rows gathered in fp8
//     (128B/row); self term exact fp32.
// ---------------------------------------------------------------------------
__global__ void __launch_bounds__(256) att_kernel(
        const float* __restrict__ emb,
        const int*   __restrict__ neighbors,
        const float* __restrict__ fc_b) {
    int warp = (blockIdx.x * blockDim.x + threadIdx.x) >> 5;
    int lane = threadIdx.x & 31;
    if (warp >= g_list_count) return;
    const int node = g_list[warp];
    const float fcb   = fc_b[0];
    const float selfv = g_self[node];

    int s = lane >> 4;            // 0 or 1
    int k = lane & 15;            // 0..15
    int nb = neighbors[(size_t)s * N_NODES * KNB + (size_t)node * KNB + k];

    float sc = g_proj[nb] + selfv + fcb;
    sc = (sc >= 0.f) ? sc : 0.2f * sc;          // leaky relu 0.2

    float m = sc;
#pragma unroll
    for (int off = 8; off; off >>= 1)
        m = fmaxf(m, __shfl_xor_sync(0xffffffffu, m, off));
    float ex = __expf(sc - m);
    float ssum = ex;
#pragma unroll
    for (int off = 8; off; off >>= 1)
        ssum += __shfl_xor_sync(0xffffffffu, ssum, off);
    float wgt = ex / ssum;

    // acc starts at (STEPS*K) * own embedding = 32 * emb[node]  (exact fp32)
    float4 me = reinterpret_cast<const float4*>(emb + (size_t)node * DIM)[lane];
    float4 acc;
    acc.x = 32.f * me.x; acc.y = 32.f * me.y;
    acc.z = 32.f * me.z; acc.w = 32.f * me.w;

    // weighted gather-accumulate over all 32 (step,neighbor) pairs, fp8 rows
#pragma unroll
    for (int j = 0; j < 32; j++) {
        float wj = __shfl_sync(0xffffffffu, wgt, j);
        int   ij = __shfl_sync(0xffffffffu, nb,  j);
        unsigned u = g_emb8[(size_t)ij * 32 + lane];
        float2 f0 = fp8x2_to_float2((unsigned short)(u & 0xffffu));
        float2 f1 = fp8x2_to_float2((unsigned short)(u >> 16));
        acc.x += wj * f0.x; acc.y += wj * f0.y;
        acc.z += wj * f1.x; acc.w += wj * f1.y;
    }
    reinterpret_cast<float4*>(g_att + (size_t)node * DIM)[lane] = acc;
}

// ---------------------------------------------------------------------------
// K3: per-edge loss partials, 2 edges per warp, fused deterministic reduce.
// ---------------------------------------------------------------------------
__global__ void __launch_bounds__(256) edge_kernel(
        const float* __restrict__ emb,
        const int*   __restrict__ edges,
        const int*   __restrict__ labels,
        const float* __restrict__ layer_b,
        float* __restrict__ out) {
    __shared__ float wsum[EDGE_WARPS_PER_BLK];
    __shared__ bool  is_last;
    int warp_in_blk = threadIdx.x >> 5;
    int lane = threadIdx.x & 31;
    int e0 = (blockIdx.x * EDGE_WARPS_PER_BLK + warp_in_blk) * EDGES_PER_WARP;

    int4 ed = *reinterpret_cast<const int4*>(edges + 2 * e0);   // s0,d0,s1,d1
    int2 lb = *reinterpret_cast<const int2*>(labels + e0);

    const float* base0 = (lb.x == 1) ? g_att : emb;
    const float* base1 = (lb.y == 1) ? g_att : emb;

    float4 se0 = reinterpret_cast<const float4*>(base0 + (size_t)ed.x * DIM)[lane];
    float4 de0 = reinterpret_cast<const float4*>(base0 + (size_t)ed.y * DIM)[lane];
    float4 se1 = reinterpret_cast<const float4*>(base1 + (size_t)ed.z * DIM)[lane];
    float4 de1 = reinterpret_cast<const float4*>(base1 + (size_t)ed.w * DIM)[lane];

    float4 c0 = reinterpret_cast<const float4*>(g_cw)[lane];
    float4 c1 = reinterpret_cast<const float4*>(g_cw + DIM)[lane];
    float4 b0 = reinterpret_cast<const float4*>(layer_b)[lane];
    float4 b1 = reinterpret_cast<const float4*>(layer_b + DIM)[lane];

    float a0 = 0.f, a1 = 0.f;
    {
        float t;
        t = (fmaxf(se0.x*c0.x+b0.x,0.f)+fmaxf(se0.x*c1.x+b1.x,0.f)) - (fmaxf(de0.x*c0.x+b0.x,0.f)+fmaxf(de0.x*c1.x+b1.x,0.f)); a0 += t*t;
        t = (fmaxf(se0.y*c0.y+b0.y,0.f)+fmaxf(se0.y*c1.y+b1.y,0.f)) - (fmaxf(de0.y*c0.y+b0.y,0.f)+fmaxf(de0.y*c1.y+b1.y,0.f)); a0 += t*t;
        t = (fmaxf(se0.z*c0.z+b0.z,0.f)+fmaxf(se0.z*c1.z+b1.z,0.f)) - (fmaxf(de0.z*c0.z+b0.z,0.f)+fmaxf(de0.z*c1.z+b1.z,0.f)); a0 += t*t;
        t = (fmaxf(se0.w*c0.w+b0.w,0.f)+fmaxf(se0.w*c1.w+b1.w,0.f)) - (fmaxf(de0.w*c0.w+b0.w,0.f)+fmaxf(de0.w*c1.w+b1.w,0.f)); a0 += t*t;
        t = (fmaxf(se1.x*c0.x+b0.x,0.f)+fmaxf(se1.x*c1.x+b1.x,0.f)) - (fmaxf(de1.x*c0.x+b0.x,0.f)+fmaxf(de1.x*c1.x+b1.x,0.f)); a1 += t*t;
        t = (fmaxf(se1.y*c0.y+b0.y,0.f)+fmaxf(se1.y*c1.y+b1.y,0.f)) - (fmaxf(de1.y*c0.y+b0.y,0.f)+fmaxf(de1.y*c1.y+b1.y,0.f)); a1 += t*t;
        t = (fmaxf(se1.z*c0.z+b0.z,0.f)+fmaxf(se1.z*c1.z+b1.z,0.f)) - (fmaxf(de1.z*c0.z+b0.z,0.f)+fmaxf(de1.z*c1.z+b1.z,0.f)); a1 += t*t;
        t = (fmaxf(se1.w*c0.w+b0.w,0.f)+fmaxf(se1.w*c1.w+b1.w,0.f)) - (fmaxf(de1.w*c0.w+b0.w,0.f)+fmaxf(de1.w*c1.w+b1.w,0.f)); a1 += t*t;
    }
#pragma unroll
    for (int off = 16; off; off >>= 1) {
        a0 += __shfl_xor_sync(0xffffffffu, a0, off);
        a1 += __shfl_xor_sync(0xffffffffu, a1, off);
    }
    if (lane == 0) {
        float inv_d = 1.f / (float)DIM;
        float p0 = expf(-a0 * inv_d);
        float p1 = expf(-a1 * inv_d);
        float l0 = (float)lb.x - p0;
        float l1 = (float)lb.y - p1;
        wsum[warp_in_blk] = 0.5f * (l0 * l0 + l1 * l1);
    }
    __syncthreads();
    if (threadIdx.x == 0) {
        float s = 0.f;
#pragma unroll
        for (int i = 0; i < EDGE_WARPS_PER_BLK; i++) s += wsum[i];
        g_partials[blockIdx.x] = s;
        __threadfence();
        int done = atomicAdd(&g_edge_count, 1);
        is_last = (done == EDGE_BLOCKS - 1);
    }
    __syncthreads();

    if (is_last) {
        __shared__ float sh[256];
        __threadfence();
        int t = threadIdx.x;
        float v = 0.f;
#pragma unroll
        for (int i = 0; i < EDGE_BLOCKS / 256; i++)
            v += g_partials[t + i * 256];
        sh[t] = v;
        __syncthreads();
#pragma unroll
        for (int stride = 128; stride; stride >>= 1) {
            if (t < stride) sh[t] += sh[t + stride];
            __syncthreads();
        }
        if (t == 0) out[0] = sh[0];
    }
}

// ---------------------------------------------------------------------------
extern "C" void kernel_launch(void* const* d_in, const int* in_sizes, int n_in,
                              void* d_out, int out_size) {
    const int*   edges     = (const int*)  d_in[0];
    const int*   labels    = (const int*)  d_in[1];
    const int*   neighbors = (const int*)  d_in[2];
    const float* emb       = (const float*)d_in[3];
    const float* fc_w      = (const float*)d_in[4];
    const float* fc_b      = (const float*)d_in[5];
    const float* layer_w   = (const float*)d_in[6];
    const float* layer_b   = (const float*)d_in[7];
    float* out = (float*)d_out;

    proj_cw_kernel<<<PROJ_BLOCKS, 256>>>(emb, fc_w, layer_w);
    mark_kernel<<<(E_EDGES + 255) / 256, 256>>>(edges, labels);
    att_kernel<<<ATT_BLOCKS, 256>>>(emb, neighbors, fc_b);
    edge_kernel<<<EDGE_BLOCKS, 256>>>(emb, edges, labels, layer_b, out);
}